// round 3
// baseline (speedup 1.0000x reference)
#include <cuda_runtime.h>

#define D 4096
#define H 64
#define S 64
#define EPSF 1e-5f

// Scratch (no allocations allowed)
__device__ float g_mix[4 * D];   // mix_r, mix_k, mix_v, mix_g
__device__ float g_rkvg[4 * D];  // r, k, v, g_lin
__device__ float g_y[D];         // gated, normalized wkv

// ---------------------------------------------------------------------------
// Kernel 1: LayerNorm(x) -> xx (= state1_out), then 4 token-mix vectors.
// 1 block, 256 threads, 16 elems/thread.
// ---------------------------------------------------------------------------
__global__ void ln_mix_kernel(const float* __restrict__ x,
                              const float* __restrict__ state1,
                              const float* __restrict__ tmk,
                              const float* __restrict__ tmv,
                              const float* __restrict__ tmr,
                              const float* __restrict__ tmg,
                              const float* __restrict__ ln1_w,
                              const float* __restrict__ ln1_b,
                              float* __restrict__ state1_out) {
    const int tid = threadIdx.x;  // 0..255
    float vals[16];
    float s = 0.f, sq = 0.f;
#pragma unroll
    for (int i = 0; i < 16; i++) {
        float v = x[tid + i * 256];
        vals[i] = v;
        s += v;
        sq += v * v;
    }
#pragma unroll
    for (int o = 16; o; o >>= 1) {
        s += __shfl_xor_sync(0xFFFFFFFFu, s, o);
        sq += __shfl_xor_sync(0xFFFFFFFFu, sq, o);
    }
    __shared__ float rs[8], rq[8];
    const int w = tid >> 5, l = tid & 31;
    if (l == 0) { rs[w] = s; rq[w] = sq; }
    __syncthreads();
    if (w == 0) {
        s = (l < 8) ? rs[l] : 0.f;
        sq = (l < 8) ? rq[l] : 0.f;
#pragma unroll
        for (int o = 4; o; o >>= 1) {
            s += __shfl_xor_sync(0xFFFFFFFFu, s, o);
            sq += __shfl_xor_sync(0xFFFFFFFFu, sq, o);
        }
        if (l == 0) { rs[0] = s; rq[0] = sq; }
    }
    __syncthreads();
    const float mean = rs[0] * (1.f / D);
    const float var = rq[0] * (1.f / D) - mean * mean;
    const float inv = rsqrtf(var + EPSF);
#pragma unroll
    for (int i = 0; i < 16; i++) {
        const int idx = tid + i * 256;
        const float xx = (vals[i] - mean) * inv * ln1_w[idx] + ln1_b[idx];
        state1_out[idx] = xx;
        const float s1 = state1[idx];
        const float d = xx - s1;
        g_mix[idx]         = s1 + d * tmr[idx];
        g_mix[D + idx]     = s1 + d * tmk[idx];
        g_mix[2 * D + idx] = s1 + d * tmv[idx];
        g_mix[3 * D + idx] = s1 + d * tmg[idx];
    }
}

// ---------------------------------------------------------------------------
// Kernel 2: fused 4-matrix GEMV. One warp per output row, float4 loads.
// 16384 rows total; grid = 2048 blocks x 256 threads (8 warps/block).
// ---------------------------------------------------------------------------
__global__ void gemv4_kernel(const float* __restrict__ Wr,
                             const float* __restrict__ Wk,
                             const float* __restrict__ Wv,
                             const float* __restrict__ Wg) {
    const int warp = threadIdx.x >> 5;
    const int lane = threadIdx.x & 31;
    const int row = blockIdx.x * 8 + warp;       // 0..16383
    const int mat = row >> 12;                   // 0..3
    const int r = row & (D - 1);

    const float* W = (mat == 0) ? Wr : (mat == 1) ? Wk : (mat == 2) ? Wv : Wg;
    const float4* __restrict__ W4 = (const float4*)(W + (size_t)r * D);
    const float4* __restrict__ x4 = (const float4*)(g_mix + mat * D);

    float ax = 0.f, ay = 0.f, az = 0.f, aw = 0.f;
#pragma unroll 8
    for (int c = lane; c < D / 4; c += 32) {
        const float4 wv = __ldg(W4 + c);
        const float4 xv = x4[c];
        ax += wv.x * xv.x;
        ay += wv.y * xv.y;
        az += wv.z * xv.z;
        aw += wv.w * xv.w;
    }
    float acc = (ax + ay) + (az + aw);
#pragma unroll
    for (int o = 16; o; o >>= 1) acc += __shfl_xor_sync(0xFFFFFFFFu, acc, o);
    if (lane == 0) g_rkvg[row] = acc;
}

// ---------------------------------------------------------------------------
// Kernel 3: per-head WKV + state2 update + InstanceNorm + SiLU gate.
// 64 blocks (one per head) x 64 threads (one per column j).
// ---------------------------------------------------------------------------
__global__ void wkv_kernel(const float* __restrict__ state2,
                           const float* __restrict__ time_decay,
                           const float* __restrict__ time_first,
                           const float* __restrict__ lnx_w,
                           const float* __restrict__ lnx_b,
                           float* __restrict__ state2_out) {
    const int h = blockIdx.x;
    const int j = threadIdx.x;  // 0..63

    __shared__ float sr[S], sk[S], std_[S];
    __shared__ float pr[2], ss[2], qq[2];

    const float r = g_rkvg[h * S + j];
    const float k = g_rkvg[D + h * S + j];
    const float v = g_rkvg[2 * D + h * S + j];
    const float g = g_rkvg[3 * D + h * S + j];
    const float tf = time_first[h * S + j];
    const float td = time_decay[h * S + j];

    sr[j] = r;
    sk[j] = k;
    std_[j] = td;

    // sum_i r_i * k_i * tf_i  (index i == thread j here)
    float p = r * k * tf;
#pragma unroll
    for (int o = 16; o; o >>= 1) p += __shfl_xor_sync(0xFFFFFFFFu, p, o);
    if ((j & 31) == 0) pr[j >> 5] = p;
    __syncthreads();
    const float sum_rktf = pr[0] + pr[1];

    const float* __restrict__ s2 = state2 + h * S * S;
    float* __restrict__ s2o = state2_out + h * S * S;

    float wkv = v * sum_rktf;
#pragma unroll 4
    for (int i = 0; i < S; i++) {
        const float sv = s2[i * S + j];
        wkv += sr[i] * sv;
        s2o[i * S + j] = sk[i] * v + sv * std_[i];
    }

    // InstanceNorm over the S columns of this head
    float s = wkv, sq = wkv * wkv;
#pragma unroll
    for (int o = 16; o; o >>= 1) {
        s += __shfl_xor_sync(0xFFFFFFFFu, s, o);
        sq += __shfl_xor_sync(0xFFFFFFFFu, sq, o);
    }
    if ((j & 31) == 0) { ss[j >> 5] = s; qq[j >> 5] = sq; }
    __syncthreads();
    const float mu = (ss[0] + ss[1]) * (1.f / S);
    const float var = (qq[0] + qq[1]) * (1.f / S) - mu * mu;
    const float inv = rsqrtf(var + EPSF);

    const float gate = g / (1.f + __expf(-g));  // SiLU
    g_y[h * S + j] = ((wkv - mu) * inv * lnx_w[h * S + j] + lnx_b[h * S + j]) * gate;
}

// ---------------------------------------------------------------------------
// Kernel 4: out = x + Wo @ y. Warp-per-row GEMV, 512 blocks x 256 threads.
// ---------------------------------------------------------------------------
__global__ void out_gemv_kernel(const float* __restrict__ Wo,
                                const float* __restrict__ x,
                                float* __restrict__ out) {
    const int warp = threadIdx.x >> 5;
    const int lane = threadIdx.x & 31;
    const int row = blockIdx.x * 8 + warp;  // 0..4095

    const float4* __restrict__ W4 = (const float4*)(Wo + (size_t)row * D);
    const float4* __restrict__ y4 = (const float4*)g_y;

    float ax = 0.f, ay = 0.f, az = 0.f, aw = 0.f;
#pragma unroll 8
    for (int c = lane; c < D / 4; c += 32) {
        const float4 wv = __ldg(W4 + c);
        const float4 yv = y4[c];
        ax += wv.x * yv.x;
        ay += wv.y * yv.y;
        az += wv.z * yv.z;
        aw += wv.w * yv.w;
    }
    float acc = (ax + ay) + (az + aw);
#pragma unroll
    for (int o = 16; o; o >>= 1) acc += __shfl_xor_sync(0xFFFFFFFFu, acc, o);
    if (lane == 0) out[row] = x[row] + acc;
}

// ---------------------------------------------------------------------------
// Launch. Output layout: [out(4096) | state1_out(4096) | state2_out(262144)]
// ---------------------------------------------------------------------------
extern "C" void kernel_launch(void* const* d_in, const int* in_sizes, int n_in,
                              void* d_out, int out_size) {
    (void)in_sizes; (void)n_in; (void)out_size;
    const float* x      = (const float*)d_in[0];
    const float* state1 = (const float*)d_in[1];
    const float* state2 = (const float*)d_in[2];
    const float* tmk    = (const float*)d_in[3];
    const float* tmv    = (const float*)d_in[4];
    const float* tmr    = (const float*)d_in[5];
    const float* tmg    = (const float*)d_in[6];
    const float* tdec   = (const float*)d_in[7];
    const float* tfirst = (const float*)d_in[8];
    const float* Wr     = (const float*)d_in[9];
    const float* Wk     = (const float*)d_in[10];
    const float* Wv     = (const float*)d_in[11];
    const float* Wg     = (const float*)d_in[12];
    const float* Wo     = (const float*)d_in[13];
    const float* ln1_w  = (const float*)d_in[14];
    const float* ln1_b  = (const float*)d_in[15];
    const float* lnx_w  = (const float*)d_in[16];
    const float* lnx_b  = (const float*)d_in[17];

    float* out        = (float*)d_out;
    float* state1_out = out + D;
    float* state2_out = out + 2 * D;

    ln_mix_kernel<<<1, 256>>>(x, state1, tmk, tmv, tmr, tmg, ln1_w, ln1_b,
                              state1_out);
    gemv4_kernel<<<2048, 256>>>(Wr, Wk, Wv, Wg);
    wkv_kernel<<<64, 64>>>(state2, tdec, tfirst, lnx_w, lnx_b, state2_out);
    out_gemv_kernel<<<512, 256>>>(Wo, x, out);
}